// round 11
// baseline (speedup 1.0000x reference)
#include <cuda_runtime.h>
#include <math.h>
#include <stdint.h>

#define BB 64
#define TT 512
#define DD 512
#define MM (BB*TT)   // 32768

typedef unsigned long long u64;

// Scratch for the precomputed projections (192 MB total)
__device__ float g_ev[MM*DD];
__device__ float g_leak[MM*DD];
__device__ float g_write[MM*DD];

// ---- packed fp32x2 helpers (Blackwell f32x2 pipe; exact IEEE fp32) ----
__device__ __forceinline__ u64 pack2(float lo, float hi) {
    u64 r; asm("mov.b64 %0, {%1, %2};" : "=l"(r) : "f"(lo), "f"(hi)); return r;
}
__device__ __forceinline__ void unpack2(u64 v, float& lo, float& hi) {
    asm("mov.b64 {%0, %1}, %2;" : "=f"(lo), "=f"(hi) : "l"(v));
}
__device__ __forceinline__ u64 ffma2(u64 a, u64 b, u64 c) {
    u64 d; asm("fma.rn.f32x2 %0, %1, %2, %3;" : "=l"(d) : "l"(a), "l"(b), "l"(c));
    return d;
}

// ---------------------------------------------------------------------------
// Kernel A: Y[m][n] = act( sum_k X[m][k]*W[k][n] + bias[n] )
// BM=128, BN=128, BK=16, 256 threads, 8x8 tile, f32x2 inner loop.
// As2 stores PRE-DUPLICATED (a,a) u64 pairs k-major.
// ---------------------------------------------------------------------------
template<int ACT>
__global__ __launch_bounds__(256, 2)
void proj_gemm(const float* __restrict__ X, const float* __restrict__ W,
               const float* __restrict__ bias, float* __restrict__ Y)
{
    constexpr int BM = 128, BN = 128, BK = 16;
    __shared__ __align__(16) u64   As2[BK*BM];   // [k][m], (a,a) pairs: 16 KB
    __shared__ __align__(16) float Bs[BK*BN];    // [k][n]: 8 KB

    const int tid = threadIdx.x;
    const int m0 = blockIdx.x * BM;
    const int n0 = blockIdx.y * BN;
    const int tx = tid & 15;
    const int ty = tid >> 4;

    const int arow = tid >> 2;          // 0..63 (rows arow, arow+64)
    const int acol = (tid & 3) * 4;     // k offset 0,4,8,12
    const int brow = tid >> 5;
    const int bcol = (tid & 31) * 4;

    u64 acc2[8][4];
    #pragma unroll
    for (int i = 0; i < 8; i++)
        #pragma unroll
        for (int j = 0; j < 4; j++) acc2[i][j] = 0ULL;

    for (int k0 = 0; k0 < DD; k0 += BK) {
        float4 a0 = *(const float4*)&X[(size_t)(m0 + arow     ) * DD + k0 + acol];
        float4 a1 = *(const float4*)&X[(size_t)(m0 + arow + 64) * DD + k0 + acol];
        float4 b0 = *(const float4*)&W[(size_t)(k0 + brow    ) * DD + n0 + bcol];
        float4 b1 = *(const float4*)&W[(size_t)(k0 + brow + 8) * DD + n0 + bcol];
        // transpose-store A as duplicated pairs: As2[k][m] = (a,a)
        As2[(acol + 0) * BM + arow] = pack2(a0.x, a0.x);
        As2[(acol + 1) * BM + arow] = pack2(a0.y, a0.y);
        As2[(acol + 2) * BM + arow] = pack2(a0.z, a0.z);
        As2[(acol + 3) * BM + arow] = pack2(a0.w, a0.w);
        As2[(acol + 0) * BM + arow + 64] = pack2(a1.x, a1.x);
        As2[(acol + 1) * BM + arow + 64] = pack2(a1.y, a1.y);
        As2[(acol + 2) * BM + arow + 64] = pack2(a1.z, a1.z);
        As2[(acol + 3) * BM + arow + 64] = pack2(a1.w, a1.w);
        *(float4*)&Bs[(brow    ) * BN + bcol] = b0;
        *(float4*)&Bs[(brow + 8) * BN + bcol] = b1;
        __syncthreads();

        #pragma unroll
        for (int kk = 0; kk < BK; kk++) {
            ulonglong2 ap0 = *(const ulonglong2*)&As2[kk * BM + ty * 8];
            ulonglong2 ap1 = *(const ulonglong2*)&As2[kk * BM + ty * 8 + 2];
            ulonglong2 ap2 = *(const ulonglong2*)&As2[kk * BM + ty * 8 + 4];
            ulonglong2 ap3 = *(const ulonglong2*)&As2[kk * BM + ty * 8 + 6];
            ulonglong2 bp0 = *(const ulonglong2*)&Bs[kk * BN + tx * 8];
            ulonglong2 bp1 = *(const ulonglong2*)&Bs[kk * BN + tx * 8 + 4];
            u64 ap[8] = { ap0.x, ap0.y, ap1.x, ap1.y, ap2.x, ap2.y, ap3.x, ap3.y };
            u64 b2[4] = { bp0.x, bp0.y, bp1.x, bp1.y };
            #pragma unroll
            for (int i = 0; i < 8; i++)
                #pragma unroll
                for (int j = 0; j < 4; j++)
                    acc2[i][j] = ffma2(ap[i], b2[j], acc2[i][j]);
        }
        __syncthreads();
    }

    #pragma unroll
    for (int i = 0; i < 8; i++) {
        const int m = m0 + ty * 8 + i;
        #pragma unroll
        for (int j = 0; j < 4; j++) {
            float lo, hi;
            unpack2(acc2[i][j], lo, hi);
            const int n = n0 + tx * 8 + 2 * j;
            float v0 = lo + bias[n];
            float v1 = hi + bias[n + 1];
            if (ACT == 1) {
                v0 = 1.0f / (1.0f + expf(-v0));
                v1 = 1.0f / (1.0f + expf(-v1));
            }
            Y[(size_t)m * DD + n]     = v0;
            Y[(size_t)m * DD + n + 1] = v1;
        }
    }
}

// ---------------------------------------------------------------------------
// Kernel B: cluster-resident scan, mbarrier-tx pipeline (R8 protocol),
// f32x2 matvec. FIX vs R9: the 64-float slice is 16 ulonglong2 (256 B),
// so the inner loop runs 16 iterations consuming all 32 w2 pairs.
// ---------------------------------------------------------------------------
#define CLUSTER_C 8
#define NCLUST 16
#define BPC 4
#define DLOC 64
#define SCAN_THREADS 512
#define SLICE_BYTES (BPC*DLOC*4)             // 1024
#define STEP_BYTES  (CLUSTER_C*SLICE_BYTES)  // 8192

__global__ __launch_bounds__(SCAN_THREADS, 1) __cluster_dims__(CLUSTER_C, 1, 1)
void scan_cluster_kernel(const float* __restrict__ Wp, const float* __restrict__ bp,
                         float* __restrict__ out)
{
    __shared__ __align__(16) float bel[2][CLUSTER_C][BPC][DLOC];  // 16 KB
    __shared__ __align__(16) float sp[BPC][8][DLOC];              // 8 KB
    __shared__ __align__(16) float stage[2][BPC][DLOC];           // 2 KB
    __shared__ __align__(8)  u64  full_mbar[2];

    const int tid     = threadIdx.x;
    const int d_local = tid & 63;
    const int ksec    = tid >> 6;        // 0..7
    const int kbase   = ksec * 64;

    uint32_t rank;
    asm("mov.u32 %0, %%cluster_ctarank;" : "=r"(rank));
    const int cluster_id = blockIdx.x / CLUSTER_C;
    const int b0    = cluster_id * BPC;
    const int dglob = (int)rank * DLOC + d_local;

    // ---- Persistent Wp slice: 32 packed k-pairs (64 fp32) in registers ----
    u64 w2[32];
    #pragma unroll
    for (int j = 0; j < 32; j++)
        w2[j] = pack2(Wp[(size_t)(kbase + 2*j    ) * DD + dglob],
                      Wp[(size_t)(kbase + 2*j + 1) * DD + dglob]);

    // ---- init belief buffer 0 + mbarriers ----
    for (int i = tid; i < CLUSTER_C * BPC * DLOC; i += SCAN_THREADS)
        (&bel[0][0][0][0])[i] = 0.0f;
    const uint32_t mb0 = (uint32_t)__cvta_generic_to_shared(&full_mbar[0]);
    const uint32_t mb1 = (uint32_t)__cvta_generic_to_shared(&full_mbar[1]);
    if (tid == 0) {
        asm volatile("mbarrier.init.shared.b64 [%0], 1;" :: "r"(mb0) : "memory");
        asm volatile("mbarrier.init.shared.b64 [%0], 1;" :: "r"(mb1) : "memory");
    }
    __syncthreads();

    // ---- reducer state: threads 0..255, one per (batch, column) ----
    const int  rb     = ksec & 3;
    const bool is_red = (tid < 256);
    float bel_prev = 0.0f;
    float bpv = 0.0f;
    size_t io_base = 0;
    if (is_red) {
        bpv = bp[dglob];
        io_base = ((size_t)(b0 + rb) * TT) * DD + dglob;
    }

    // one cluster sync: all CTAs' bel[0] + mbarriers ready before any traffic
    asm volatile("barrier.cluster.arrive.aligned;" ::: "memory");
    asm volatile("barrier.cluster.wait.aligned;"   ::: "memory");

    int ph0 = 0, ph1 = 0;

    for (int t = 0; t < TT; t++) {
        const int cur = t & 1;
        const int nxt = cur ^ 1;

        // gate prefetch BEFORE the wait: DRAM latency hides under wait+matvec
        float evv = 0.f, lkv = 0.f, wrv = 0.f;
        if (is_red) {
            const size_t idx = io_base + (size_t)t * DD;
            evv = g_ev[idx];
            lkv = g_leak[idx];
            wrv = g_write[idx];
        }

        // ---- wait for bel[cur] (written during step t-1) ----
        if (t > 0) {
            const uint32_t mb = cur ? mb1 : mb0;
            const int ph = cur ? ph1 : ph0;
            uint32_t done;
            asm volatile(
                "{\n\t.reg .pred p;\n\t"
                "mbarrier.try_wait.parity.acquire.cta.shared::cta.b64 p, [%1], %2;\n\t"
                "selp.b32 %0, 1, 0, p;\n\t}"
                : "=r"(done) : "r"(mb), "r"(ph) : "memory");
            if (!done) {
                asm volatile(
                    "{\n\t.reg .pred P1;\n\t"
                    "W%=:\n\t"
                    "mbarrier.try_wait.parity.acquire.cta.shared::cta.b64 P1, [%0], %1, 0x989680;\n\t"
                    "@P1 bra.uni D%=;\n\t"
                    "bra.uni W%=;\n\t"
                    "D%=:\n\t}"
                    :: "r"(mb), "r"(ph) : "memory");
            }
            if (cur) ph1 ^= 1; else ph0 ^= 1;
        }

        // ---- matvec partials: 4-batch interleave on the f32x2 pipe ----
        // 64-float slice = 16 ulonglong2 (256 B); 32 FFMA2 per batch row.
        const ulonglong2* bl0 = (const ulonglong2*)&bel[cur][ksec][0][0];
        const ulonglong2* bl1 = (const ulonglong2*)&bel[cur][ksec][1][0];
        const ulonglong2* bl2 = (const ulonglong2*)&bel[cur][ksec][2][0];
        const ulonglong2* bl3 = (const ulonglong2*)&bel[cur][ksec][3][0];
        u64 a0 = 0ULL, a1 = 0ULL, a2 = 0ULL, a3 = 0ULL;
        #pragma unroll
        for (int j = 0; j < 16; j++) {
            const ulonglong2 v0 = bl0[j];
            const ulonglong2 v1 = bl1[j];
            const ulonglong2 v2 = bl2[j];
            const ulonglong2 v3 = bl3[j];
            a0 = ffma2(v0.x, w2[2*j  ], a0);
            a0 = ffma2(v0.y, w2[2*j+1], a0);
            a1 = ffma2(v1.x, w2[2*j  ], a1);
            a1 = ffma2(v1.y, w2[2*j+1], a1);
            a2 = ffma2(v2.x, w2[2*j  ], a2);
            a2 = ffma2(v2.y, w2[2*j+1], a2);
            a3 = ffma2(v3.x, w2[2*j  ], a3);
            a3 = ffma2(v3.y, w2[2*j+1], a3);
        }
        {
            float lo, hi;
            unpack2(a0, lo, hi); sp[0][ksec][d_local] = lo + hi;
            unpack2(a1, lo, hi); sp[1][ksec][d_local] = lo + hi;
            unpack2(a2, lo, hi); sp[2][ksec][d_local] = lo + hi;
            unpack2(a3, lo, hi); sp[3][ksec][d_local] = lo + hi;
        }
        __syncthreads();

        // ---- reduce + gates -> staging ----
        if (is_red) {
            float s = 0.f;
            #pragma unroll
            for (int q = 0; q < 8; q++) s += sp[rb][q][d_local];
            const float cand = tanhf(s + bpv + evv);
            const float nb   = lkv * bel_prev + wrv * cand;
            bel_prev = nb;
            stage[cur][rb][d_local] = nb;
            out[io_base + (size_t)t * DD] = nb;
        }
        __syncthreads();   // staging complete before async source reads

        // ---- broadcast: 8x 1KB bulk copies w/ complete_tx on dest barrier ----
        if (t < TT - 1 && tid == 0) {
            asm volatile("fence.proxy.async.shared::cta;" ::: "memory");
            const uint32_t mb_l = nxt ? mb1 : mb0;
            asm volatile(
                "mbarrier.arrive.expect_tx.shared.b64 _, [%0], %1;"
                :: "r"(mb_l), "r"((uint32_t)STEP_BYTES) : "memory");
            const uint32_t src = (uint32_t)__cvta_generic_to_shared(&stage[cur][0][0]);
            const uint32_t dst_l =
                (uint32_t)__cvta_generic_to_shared(&bel[nxt][rank][0][0]);
            #pragma unroll
            for (int p = 0; p < CLUSTER_C; p++) {
                uint32_t dst_r, mb_r;
                asm("mapa.shared::cluster.u32 %0, %1, %2;"
                    : "=r"(dst_r) : "r"(dst_l), "r"(p));
                asm("mapa.shared::cluster.u32 %0, %1, %2;"
                    : "=r"(mb_r) : "r"(mb_l), "r"(p));
                asm volatile(
                    "cp.async.bulk.shared::cluster.shared::cta.mbarrier::complete_tx::bytes "
                    "[%0], [%1], %2, [%3];"
                    :: "r"(dst_r), "r"(src), "r"((uint32_t)SLICE_BYTES), "r"(mb_r)
                    : "memory");
            }
        }
    }
}

// ---------------------------------------------------------------------------
// Launch
// ---------------------------------------------------------------------------
extern "C" void kernel_launch(void* const* d_in, const int* in_sizes, int n_in,
                              void* d_out, int out_size)
{
    const float* evseq = (const float*)d_in[0];
    const float* We    = (const float*)d_in[1];
    const float* be    = (const float*)d_in[2];
    const float* Wp    = (const float*)d_in[3];
    const float* bp    = (const float*)d_in[4];
    const float* Wl    = (const float*)d_in[5];
    const float* bl    = (const float*)d_in[6];
    const float* Ww    = (const float*)d_in[7];
    const float* bw    = (const float*)d_in[8];
    float* out = (float*)d_out;

    float *p_ev, *p_leak, *p_write;
    cudaGetSymbolAddress((void**)&p_ev,    g_ev);
    cudaGetSymbolAddress((void**)&p_leak,  g_leak);
    cudaGetSymbolAddress((void**)&p_write, g_write);

    dim3 grid(MM / 128, DD / 128);
    dim3 blk(256);
    proj_gemm<0><<<grid, blk>>>(evseq, We, be, p_ev);
    proj_gemm<1><<<grid, blk>>>(evseq, Wl, bl, p_leak);
    proj_gemm<1><<<grid, blk>>>(evseq, Ww, bw, p_write);

    scan_cluster_kernel<<<NCLUST * CLUSTER_C, SCAN_THREADS>>>(Wp, bp, out);
}

// round 12
// speedup vs baseline: 1.1271x; 1.1271x over previous
#include <cuda_runtime.h>
#include <math.h>
#include <stdint.h>

#define BB 64
#define TT 512
#define DD 512
#define MM (BB*TT)   // 32768

typedef unsigned long long u64;

// Scratch for the precomputed projections (192 MB total)
__device__ float g_ev[MM*DD];
__device__ float g_leak[MM*DD];
__device__ float g_write[MM*DD];

// ---- packed fp32x2 helpers (Blackwell f32x2 pipe; exact IEEE fp32) ----
__device__ __forceinline__ u64 pack2(float lo, float hi) {
    u64 r; asm("mov.b64 %0, {%1, %2};" : "=l"(r) : "f"(lo), "f"(hi)); return r;
}
__device__ __forceinline__ void unpack2(u64 v, float& lo, float& hi) {
    asm("mov.b64 {%0, %1}, %2;" : "=f"(lo), "=f"(hi) : "l"(v));
}
__device__ __forceinline__ u64 ffma2(u64 a, u64 b, u64 c) {
    u64 d; asm("fma.rn.f32x2 %0, %1, %2, %3;" : "=l"(d) : "l"(a), "l"(b), "l"(c));
    return d;
}

// fast tanh: sign-safe, __expf-based (MUFU path), ~1e-6 rel error
__device__ __forceinline__ float fast_tanh(float x) {
    const float a = fabsf(x);
    const float t = __expf(-2.0f * a);
    const float r = __fdividef(1.0f - t, 1.0f + t);
    return copysignf(r, x);
}

// ---------------------------------------------------------------------------
// Kernel A (R8-proven version): Y[m][n] = act( sum_k X[m][k]*W[k][n] + b[n] )
// BM=128, BN=128, BK=16, 256 threads, 8x8 tile, f32x2 inner loop,
// k-major float As (2x LDS.128 per kk for 'a').
// ---------------------------------------------------------------------------
template<int ACT>
__global__ __launch_bounds__(256, 2)
void proj_gemm(const float* __restrict__ X, const float* __restrict__ W,
               const float* __restrict__ bias, float* __restrict__ Y)
{
    constexpr int BM = 128, BN = 128, BK = 16;
    __shared__ __align__(16) float As[BK*BM];   // [k][m]  (m contiguous)
    __shared__ __align__(16) float Bs[BK*BN];   // [k][n]  (n contiguous)

    const int tid = threadIdx.x;
    const int m0 = blockIdx.x * BM;
    const int n0 = blockIdx.y * BN;
    const int tx = tid & 15;
    const int ty = tid >> 4;

    const int arow = tid >> 2;          // 0..63 (rows arow, arow+64)
    const int acol = (tid & 3) * 4;     // k offset 0,4,8,12
    const int brow = tid >> 5;
    const int bcol = (tid & 31) * 4;

    u64 acc2[8][4];
    #pragma unroll
    for (int i = 0; i < 8; i++)
        #pragma unroll
        for (int j = 0; j < 4; j++) acc2[i][j] = 0ULL;

    for (int k0 = 0; k0 < DD; k0 += BK) {
        float4 a0 = *(const float4*)&X[(size_t)(m0 + arow     ) * DD + k0 + acol];
        float4 a1 = *(const float4*)&X[(size_t)(m0 + arow + 64) * DD + k0 + acol];
        float4 b0 = *(const float4*)&W[(size_t)(k0 + brow    ) * DD + n0 + bcol];
        float4 b1 = *(const float4*)&W[(size_t)(k0 + brow + 8) * DD + n0 + bcol];
        // transpose-store A: As[k][m]
        As[(acol + 0) * BM + arow] = a0.x;
        As[(acol + 1) * BM + arow] = a0.y;
        As[(acol + 2) * BM + arow] = a0.z;
        As[(acol + 3) * BM + arow] = a0.w;
        As[(acol + 0) * BM + arow + 64] = a1.x;
        As[(acol + 1) * BM + arow + 64] = a1.y;
        As[(acol + 2) * BM + arow + 64] = a1.z;
        As[(acol + 3) * BM + arow + 64] = a1.w;
        *(float4*)&Bs[(brow    ) * BN + bcol] = b0;
        *(float4*)&Bs[(brow + 8) * BN + bcol] = b1;
        __syncthreads();

        #pragma unroll
        for (int kk = 0; kk < BK; kk++) {
            float4 aA = *(const float4*)&As[kk * BM + ty * 8];
            float4 aB = *(const float4*)&As[kk * BM + ty * 8 + 4];
            ulonglong2 bp0 = *(const ulonglong2*)&Bs[kk * BN + tx * 8];
            ulonglong2 bp1 = *(const ulonglong2*)&Bs[kk * BN + tx * 8 + 4];
            u64 b2[4] = { bp0.x, bp0.y, bp1.x, bp1.y };
            float av[8] = { aA.x, aA.y, aA.z, aA.w, aB.x, aB.y, aB.z, aB.w };
            #pragma unroll
            for (int i = 0; i < 8; i++) {
                const u64 ap = pack2(av[i], av[i]);
                #pragma unroll
                for (int j = 0; j < 4; j++)
                    acc2[i][j] = ffma2(ap, b2[j], acc2[i][j]);
            }
        }
        __syncthreads();
    }

    #pragma unroll
    for (int i = 0; i < 8; i++) {
        const int m = m0 + ty * 8 + i;
        #pragma unroll
        for (int j = 0; j < 4; j++) {
            float lo, hi;
            unpack2(acc2[i][j], lo, hi);
            const int n = n0 + tx * 8 + 2 * j;
            float v0 = lo + bias[n];
            float v1 = hi + bias[n + 1];
            if (ACT == 1) {
                v0 = 1.0f / (1.0f + expf(-v0));
                v1 = 1.0f / (1.0f + expf(-v1));
            }
            Y[(size_t)m * DD + n]     = v0;
            Y[(size_t)m * DD + n + 1] = v1;
        }
    }
}

// ---------------------------------------------------------------------------
// Kernel B: cluster-resident scan, mbarrier-tx pipeline. R8-proven scalar
// matvec + protocol, with tail cuts:
//   - the 8 peer bulk-copies are issued in PARALLEL by lane 0 of warps 0..7
//   - second sync is a named barrier over threads 0..255 only (warps 8-15
//     skip straight to the next mbarrier wait; ordering preserved
//     transitively through the wait)
//   - fast_tanh on the serial chain
// ---------------------------------------------------------------------------
#define CLUSTER_C 8
#define NCLUST 16
#define BPC 4
#define DLOC 64
#define SCAN_THREADS 512
#define SLICE_BYTES (BPC*DLOC*4)             // 1024
#define STEP_BYTES  (CLUSTER_C*SLICE_BYTES)  // 8192

__global__ __launch_bounds__(SCAN_THREADS, 1) __cluster_dims__(CLUSTER_C, 1, 1)
void scan_cluster_kernel(const float* __restrict__ Wp, const float* __restrict__ bp,
                         float* __restrict__ out)
{
    __shared__ __align__(16) float bel[2][CLUSTER_C][BPC][DLOC];  // 16 KB
    __shared__ __align__(16) float sp[BPC][8][DLOC];              // 8 KB
    __shared__ __align__(16) float stage[2][BPC][DLOC];           // 2 KB
    __shared__ __align__(8)  u64  full_mbar[2];

    const int tid     = threadIdx.x;
    const int d_local = tid & 63;
    const int ksec    = tid >> 6;        // 0..7
    const int kbase   = ksec * 64;

    uint32_t rank;
    asm("mov.u32 %0, %%cluster_ctarank;" : "=r"(rank));
    const int cluster_id = blockIdx.x / CLUSTER_C;
    const int b0    = cluster_id * BPC;
    const int dglob = (int)rank * DLOC + d_local;

    // ---- Persistent Wp slice in registers ----
    float w[64];
    #pragma unroll
    for (int j = 0; j < 64; j++)
        w[j] = Wp[(size_t)(kbase + j) * DD + dglob];

    // ---- init belief buffer 0 + mbarriers ----
    for (int i = tid; i < CLUSTER_C * BPC * DLOC; i += SCAN_THREADS)
        (&bel[0][0][0][0])[i] = 0.0f;
    const uint32_t mb0 = (uint32_t)__cvta_generic_to_shared(&full_mbar[0]);
    const uint32_t mb1 = (uint32_t)__cvta_generic_to_shared(&full_mbar[1]);
    if (tid == 0) {
        asm volatile("mbarrier.init.shared.b64 [%0], 1;" :: "r"(mb0) : "memory");
        asm volatile("mbarrier.init.shared.b64 [%0], 1;" :: "r"(mb1) : "memory");
    }
    __syncthreads();

    // ---- reducer state: threads 0..255 (warps 0..7), one per (batch,col) ----
    const int  rb     = ksec & 3;
    const bool is_red = (tid < 256);
    float bel_prev = 0.0f;
    float bpv = 0.0f;
    size_t io_base = 0;
    if (is_red) {
        bpv = bp[dglob];
        io_base = ((size_t)(b0 + rb) * TT) * DD + dglob;
    }

    // one cluster sync: all CTAs' bel[0] + mbarriers ready before any traffic
    asm volatile("barrier.cluster.arrive.aligned;" ::: "memory");
    asm volatile("barrier.cluster.wait.aligned;"   ::: "memory");

    int ph0 = 0, ph1 = 0;

    for (int t = 0; t < TT; t++) {
        const int cur = t & 1;
        const int nxt = cur ^ 1;

        // gate prefetch BEFORE the wait: DRAM latency hides under wait+matvec
        float evv = 0.f, lkv = 0.f, wrv = 0.f;
        if (is_red) {
            const size_t idx = io_base + (size_t)t * DD;
            evv = g_ev[idx];
            lkv = g_leak[idx];
            wrv = g_write[idx];
        }

        // ---- wait for bel[cur] (written during step t-1) ----
        if (t > 0) {
            const uint32_t mb = cur ? mb1 : mb0;
            const int ph = cur ? ph1 : ph0;
            uint32_t done;
            asm volatile(
                "{\n\t.reg .pred p;\n\t"
                "mbarrier.try_wait.parity.acquire.cta.shared::cta.b64 p, [%1], %2;\n\t"
                "selp.b32 %0, 1, 0, p;\n\t}"
                : "=r"(done) : "r"(mb), "r"(ph) : "memory");
            if (!done) {
                asm volatile(
                    "{\n\t.reg .pred P1;\n\t"
                    "W%=:\n\t"
                    "mbarrier.try_wait.parity.acquire.cta.shared::cta.b64 P1, [%0], %1, 0x989680;\n\t"
                    "@P1 bra.uni D%=;\n\t"
                    "bra.uni W%=;\n\t"
                    "D%=:\n\t}"
                    :: "r"(mb), "r"(ph) : "memory");
            }
            if (cur) ph1 ^= 1; else ph0 ^= 1;
        }

        // ---- matvec partials: 4-batch interleave, scalar fma (R8-proven) ----
        const float4* bl0 = (const float4*)&bel[cur][ksec][0][0];
        const float4* bl1 = (const float4*)&bel[cur][ksec][1][0];
        const float4* bl2 = (const float4*)&bel[cur][ksec][2][0];
        const float4* bl3 = (const float4*)&bel[cur][ksec][3][0];
        float a0 = 0.f, a1 = 0.f, a2 = 0.f, a3 = 0.f;
        #pragma unroll
        for (int j4 = 0; j4 < 16; j4++) {
            const float4 v0 = bl0[j4];
            const float4 v1 = bl1[j4];
            const float4 v2 = bl2[j4];
            const float4 v3 = bl3[j4];
            a0 = fmaf(v0.x, w[4*j4+0], a0);
            a0 = fmaf(v0.y, w[4*j4+1], a0);
            a0 = fmaf(v0.z, w[4*j4+2], a0);
            a0 = fmaf(v0.w, w[4*j4+3], a0);
            a1 = fmaf(v1.x, w[4*j4+0], a1);
            a1 = fmaf(v1.y, w[4*j4+1], a1);
            a1 = fmaf(v1.z, w[4*j4+2], a1);
            a1 = fmaf(v1.w, w[4*j4+3], a1);
            a2 = fmaf(v2.x, w[4*j4+0], a2);
            a2 = fmaf(v2.y, w[4*j4+1], a2);
            a2 = fmaf(v2.z, w[4*j4+2], a2);
            a2 = fmaf(v2.w, w[4*j4+3], a2);
            a3 = fmaf(v3.x, w[4*j4+0], a3);
            a3 = fmaf(v3.y, w[4*j4+1], a3);
            a3 = fmaf(v3.z, w[4*j4+2], a3);
            a3 = fmaf(v3.w, w[4*j4+3], a3);
        }
        sp[0][ksec][d_local] = a0;
        sp[1][ksec][d_local] = a1;
        sp[2][ksec][d_local] = a2;
        sp[3][ksec][d_local] = a3;
        __syncthreads();   // sync#1: all partials visible to reducers

        if (is_red) {
            // ---- reduce + gates -> staging ----
            float s = 0.f;
            #pragma unroll
            for (int q = 0; q < 8; q++) s += sp[rb][q][d_local];
            const float cand = fast_tanh(s + bpv + evv);
            const float nb   = lkv * bel_prev + wrv * cand;
            bel_prev = nb;
            stage[cur][rb][d_local] = nb;
            out[io_base + (size_t)t * DD] = nb;

            // sync#2: named barrier over the 256 reducer threads only
            asm volatile("bar.sync 1, 256;" ::: "memory");

            // ---- broadcast: warp w's lane 0 sends my slice to peer w ----
            if (t < TT - 1 && (tid & 31) == 0) {
                const int peer = tid >> 5;   // 0..7
                asm volatile("fence.proxy.async.shared::cta;" ::: "memory");
                const uint32_t mb_l = nxt ? mb1 : mb0;
                if (tid == 0) {
                    // arm my own barrier: expect the full 8KB for next phase
                    asm volatile(
                        "mbarrier.arrive.expect_tx.shared.b64 _, [%0], %1;"
                        :: "r"(mb_l), "r"((uint32_t)STEP_BYTES) : "memory");
                }
                const uint32_t src =
                    (uint32_t)__cvta_generic_to_shared(&stage[cur][0][0]);
                const uint32_t dst_l =
                    (uint32_t)__cvta_generic_to_shared(&bel[nxt][rank][0][0]);
                uint32_t dst_r, mb_r;
                asm("mapa.shared::cluster.u32 %0, %1, %2;"
                    : "=r"(dst_r) : "r"(dst_l), "r"(peer));
                asm("mapa.shared::cluster.u32 %0, %1, %2;"
                    : "=r"(mb_r) : "r"(mb_l), "r"(peer));
                asm volatile(
                    "cp.async.bulk.shared::cluster.shared::cta.mbarrier::complete_tx::bytes "
                    "[%0], [%1], %2, [%3];"
                    :: "r"(dst_r), "r"(src), "r"((uint32_t)SLICE_BYTES), "r"(mb_r)
                    : "memory");
            }
        }
        // warps 8..15 fall through directly to the next wait; their sp
        // overwrite at t+1 is ordered by wait(t+1) <= my broadcast(t)
        // <= bar.sync1(t) <= reducers' sp reads(t).
    }
}

// ---------------------------------------------------------------------------
// Launch
// ---------------------------------------------------------------------------
extern "C" void kernel_launch(void* const* d_in, const int* in_sizes, int n_in,
                              void* d_out, int out_size)
{
    const float* evseq = (const float*)d_in[0];
    const float* We    = (const float*)d_in[1];
    const float* be    = (const float*)d_in[2];
    const float* Wp    = (const float*)d_in[3];
    const float* bp    = (const float*)d_in[4];
    const float* Wl    = (const float*)d_in[5];
    const float* bl    = (const float*)d_in[6];
    const float* Ww    = (const float*)d_in[7];
    const float* bw    = (const float*)d_in[8];
    float* out = (float*)d_out;

    float *p_ev, *p_leak, *p_write;
    cudaGetSymbolAddress((void**)&p_ev,    g_ev);
    cudaGetSymbolAddress((void**)&p_leak,  g_leak);
    cudaGetSymbolAddress((void**)&p_write, g_write);

    dim3 grid(MM / 128, DD / 128);
    dim3 blk(256);
    proj_gemm<0><<<grid, blk>>>(evseq, We, be, p_ev);
    proj_gemm<1><<<grid, blk>>>(evseq, Wl, bl, p_leak);
    proj_gemm<1><<<grid, blk>>>(evseq, Ww, bw, p_write);

    scan_cluster_kernel<<<NCLUST * CLUSTER_C, SCAN_THREADS>>>(Wp, bp, out);
}

// round 13
// speedup vs baseline: 1.2109x; 1.0744x over previous
#include <cuda_runtime.h>
#include <math.h>
#include <stdint.h>

#define BB 64
#define TT 512
#define DD 512
#define MM (BB*TT)   // 32768

typedef unsigned long long u64;

// Scratch for the precomputed projections (192 MB total)
__device__ float g_ev[MM*DD];
__device__ float g_leak[MM*DD];
__device__ float g_write[MM*DD];

// ---- packed fp32x2 helpers (Blackwell f32x2 pipe; exact IEEE fp32) ----
__device__ __forceinline__ u64 pack2(float lo, float hi) {
    u64 r; asm("mov.b64 %0, {%1, %2};" : "=l"(r) : "f"(lo), "f"(hi)); return r;
}
__device__ __forceinline__ void unpack2(u64 v, float& lo, float& hi) {
    asm("mov.b64 {%0, %1}, %2;" : "=f"(lo), "=f"(hi) : "l"(v));
}
__device__ __forceinline__ u64 ffma2(u64 a, u64 b, u64 c) {
    u64 d; asm("fma.rn.f32x2 %0, %1, %2, %3;" : "=l"(d) : "l"(a), "l"(b), "l"(c));
    return d;
}

// fast tanh: sign-safe, __expf-based (MUFU path), ~1e-6 rel error
__device__ __forceinline__ float fast_tanh(float x) {
    const float a = fabsf(x);
    const float t = __expf(-2.0f * a);
    const float r = __fdividef(1.0f - t, 1.0f + t);
    return copysignf(r, x);
}

// ---------------------------------------------------------------------------
// Kernel A: Y[m][n] = act( sum_k X[m][k]*W[k][n] + b[n] )
// BM=128, BN=128, BK=16, 256 threads, 8x8 tile, f32x2 inner loop,
// k-major As. NEW: register-prefetch double buffering — tile k0+1 global
// loads issue before computing tile k0, hiding gmem latency under compute.
// ---------------------------------------------------------------------------
template<int ACT>
__global__ __launch_bounds__(256, 2)
void proj_gemm(const float* __restrict__ X, const float* __restrict__ W,
               const float* __restrict__ bias, float* __restrict__ Y)
{
    constexpr int BM = 128, BN = 128, BK = 16;
    __shared__ __align__(16) float As[BK*BM];   // [k][m]  (m contiguous)
    __shared__ __align__(16) float Bs[BK*BN];   // [k][n]  (n contiguous)

    const int tid = threadIdx.x;
    const int m0 = blockIdx.x * BM;
    const int n0 = blockIdx.y * BN;
    const int tx = tid & 15;
    const int ty = tid >> 4;

    const int arow = tid >> 2;          // 0..63 (rows arow, arow+64)
    const int acol = (tid & 3) * 4;     // k offset 0,4,8,12
    const int brow = tid >> 5;
    const int bcol = (tid & 31) * 4;

    u64 acc2[8][4];
    #pragma unroll
    for (int i = 0; i < 8; i++)
        #pragma unroll
        for (int j = 0; j < 4; j++) acc2[i][j] = 0ULL;

    // prologue: tile 0 -> SMEM
    {
        float4 a0 = *(const float4*)&X[(size_t)(m0 + arow     ) * DD + acol];
        float4 a1 = *(const float4*)&X[(size_t)(m0 + arow + 64) * DD + acol];
        float4 b0 = *(const float4*)&W[(size_t)(brow    ) * DD + n0 + bcol];
        float4 b1 = *(const float4*)&W[(size_t)(brow + 8) * DD + n0 + bcol];
        As[(acol + 0) * BM + arow] = a0.x;
        As[(acol + 1) * BM + arow] = a0.y;
        As[(acol + 2) * BM + arow] = a0.z;
        As[(acol + 3) * BM + arow] = a0.w;
        As[(acol + 0) * BM + arow + 64] = a1.x;
        As[(acol + 1) * BM + arow + 64] = a1.y;
        As[(acol + 2) * BM + arow + 64] = a1.z;
        As[(acol + 3) * BM + arow + 64] = a1.w;
        *(float4*)&Bs[(brow    ) * BN + bcol] = b0;
        *(float4*)&Bs[(brow + 8) * BN + bcol] = b1;
    }
    __syncthreads();

    for (int k0 = 0; k0 < DD; k0 += BK) {
        const bool more = (k0 + BK < DD);
        float4 na0, na1, nb0, nb1;
        if (more) {   // prefetch next tile into registers (latency hidden)
            na0 = *(const float4*)&X[(size_t)(m0 + arow     ) * DD + k0 + BK + acol];
            na1 = *(const float4*)&X[(size_t)(m0 + arow + 64) * DD + k0 + BK + acol];
            nb0 = *(const float4*)&W[(size_t)(k0 + BK + brow    ) * DD + n0 + bcol];
            nb1 = *(const float4*)&W[(size_t)(k0 + BK + brow + 8) * DD + n0 + bcol];
        }

        #pragma unroll
        for (int kk = 0; kk < BK; kk++) {
            float4 aA = *(const float4*)&As[kk * BM + ty * 8];
            float4 aB = *(const float4*)&As[kk * BM + ty * 8 + 4];
            ulonglong2 bp0 = *(const ulonglong2*)&Bs[kk * BN + tx * 8];
            ulonglong2 bp1 = *(const ulonglong2*)&Bs[kk * BN + tx * 8 + 4];
            u64 b2[4] = { bp0.x, bp0.y, bp1.x, bp1.y };
            float av[8] = { aA.x, aA.y, aA.z, aA.w, aB.x, aB.y, aB.z, aB.w };
            #pragma unroll
            for (int i = 0; i < 8; i++) {
                const u64 ap = pack2(av[i], av[i]);
                #pragma unroll
                for (int j = 0; j < 4; j++)
                    acc2[i][j] = ffma2(ap, b2[j], acc2[i][j]);
            }
        }

        if (more) {
            __syncthreads();   // everyone done reading current tiles
            As[(acol + 0) * BM + arow] = na0.x;
            As[(acol + 1) * BM + arow] = na0.y;
            As[(acol + 2) * BM + arow] = na0.z;
            As[(acol + 3) * BM + arow] = na0.w;
            As[(acol + 0) * BM + arow + 64] = na1.x;
            As[(acol + 1) * BM + arow + 64] = na1.y;
            As[(acol + 2) * BM + arow + 64] = na1.z;
            As[(acol + 3) * BM + arow + 64] = na1.w;
            *(float4*)&Bs[(brow    ) * BN + bcol] = nb0;
            *(float4*)&Bs[(brow + 8) * BN + bcol] = nb1;
            __syncthreads();
        }
    }

    #pragma unroll
    for (int i = 0; i < 8; i++) {
        const int m = m0 + ty * 8 + i;
        #pragma unroll
        for (int j = 0; j < 4; j++) {
            float lo, hi;
            unpack2(acc2[i][j], lo, hi);
            const int n = n0 + tx * 8 + 2 * j;
            float v0 = lo + bias[n];
            float v1 = hi + bias[n + 1];
            if (ACT == 1) {
                v0 = 1.0f / (1.0f + expf(-v0));
                v1 = 1.0f / (1.0f + expf(-v1));
            }
            Y[(size_t)m * DD + n]     = v0;
            Y[(size_t)m * DD + n + 1] = v1;
        }
    }
}

// ---------------------------------------------------------------------------
// Kernel B: cluster-resident scan with PER-SOURCE slot mbarriers.
//   Warp-pair ksec=q reads only rank q's slice, so it waits only on slot q's
//   1KB arrival — peer skew overlaps with matvec instead of preceding it.
//   Sender r targets slot r at every destination (1KB bulk copy each).
// ---------------------------------------------------------------------------
#define CLUSTER_C 8
#define NCLUST 16
#define BPC 4
#define DLOC 64
#define SCAN_THREADS 512
#define SLICE_BYTES (BPC*DLOC*4)             // 1024

__global__ __launch_bounds__(SCAN_THREADS, 1) __cluster_dims__(CLUSTER_C, 1, 1)
void scan_cluster_kernel(const float* __restrict__ Wp, const float* __restrict__ bp,
                         float* __restrict__ out)
{
    __shared__ __align__(16) float bel[2][CLUSTER_C][BPC][DLOC];  // 16 KB
    __shared__ __align__(16) float sp[BPC][8][DLOC];              // 8 KB
    __shared__ __align__(16) float stage[2][BPC][DLOC];           // 2 KB
    __shared__ __align__(8)  u64  sb[2][CLUSTER_C];               // slot barriers

    const int tid     = threadIdx.x;
    const int d_local = tid & 63;
    const int ksec    = tid >> 6;        // 0..7 == source rank this thread reads
    const int kbase   = ksec * 64;

    uint32_t rank;
    asm("mov.u32 %0, %%cluster_ctarank;" : "=r"(rank));
    const int cluster_id = blockIdx.x / CLUSTER_C;
    const int b0    = cluster_id * BPC;
    const int dglob = (int)rank * DLOC + d_local;

    // ---- Persistent Wp slice in registers ----
    float w[64];
    #pragma unroll
    for (int j = 0; j < 64; j++)
        w[j] = Wp[(size_t)(kbase + j) * DD + dglob];

    // ---- init belief buffer 0 + slot mbarriers ----
    for (int i = tid; i < CLUSTER_C * BPC * DLOC; i += SCAN_THREADS)
        (&bel[0][0][0][0])[i] = 0.0f;
    if (tid < 2 * CLUSTER_C) {
        const uint32_t mb = (uint32_t)__cvta_generic_to_shared(&sb[0][0]) + tid * 8;
        asm volatile("mbarrier.init.shared.b64 [%0], 1;" :: "r"(mb) : "memory");
    }
    __syncthreads();

    const uint32_t sb_base = (uint32_t)__cvta_generic_to_shared(&sb[0][0]);
    // this thread's wait barrier addresses (slot = ksec), per buffer
    const uint32_t my_mb[2] = { sb_base + (uint32_t)ksec * 8,
                                sb_base + (uint32_t)(CLUSTER_C + ksec) * 8 };

    // ---- reducer state: threads 0..255 (warps 0..7), one per (batch,col) ----
    const int  rb     = ksec & 3;
    const bool is_red = (tid < 256);
    float bel_prev = 0.0f;
    float bpv = 0.0f;
    size_t io_base = 0;
    if (is_red) {
        bpv = bp[dglob];
        io_base = ((size_t)(b0 + rb) * TT) * DD + dglob;
    }

    // one cluster sync: all CTAs' bel[0] + barriers ready before any traffic
    asm volatile("barrier.cluster.arrive.aligned;" ::: "memory");
    asm volatile("barrier.cluster.wait.aligned;"   ::: "memory");

    int ph0 = 0, ph1 = 0;

    for (int t = 0; t < TT; t++) {
        const int cur = t & 1;
        const int nxt = cur ^ 1;

        // gate prefetch BEFORE the wait: DRAM latency hides under wait+matvec
        float evv = 0.f, lkv = 0.f, wrv = 0.f;
        if (is_red) {
            const size_t idx = io_base + (size_t)t * DD;
            evv = g_ev[idx];
            lkv = g_leak[idx];
            wrv = g_write[idx];
        }

        // ---- wait ONLY for my source slot (slice ksec of phase cur) ----
        if (t > 0) {
            const uint32_t mb = my_mb[cur];
            const int ph = cur ? ph1 : ph0;
            uint32_t done;
            asm volatile(
                "{\n\t.reg .pred p;\n\t"
                "mbarrier.try_wait.parity.acquire.cta.shared::cta.b64 p, [%1], %2;\n\t"
                "selp.b32 %0, 1, 0, p;\n\t}"
                : "=r"(done) : "r"(mb), "r"(ph) : "memory");
            if (!done) {
                asm volatile(
                    "{\n\t.reg .pred P1;\n\t"
                    "W%=:\n\t"
                    "mbarrier.try_wait.parity.acquire.cta.shared::cta.b64 P1, [%0], %1, 0x989680;\n\t"
                    "@P1 bra.uni D%=;\n\t"
                    "bra.uni W%=;\n\t"
                    "D%=:\n\t}"
                    :: "r"(mb), "r"(ph) : "memory");
            }
        }
        // all threads keep slot-parity in lockstep
        if (t > 0) { if (cur) ph1 ^= 1; else ph0 ^= 1; }

        // ---- matvec partials: 4-batch interleave (R8-proven structure) ----
        const float4* bl0 = (const float4*)&bel[cur][ksec][0][0];
        const float4* bl1 = (const float4*)&bel[cur][ksec][1][0];
        const float4* bl2 = (const float4*)&bel[cur][ksec][2][0];
        const float4* bl3 = (const float4*)&bel[cur][ksec][3][0];
        float a0 = 0.f, a1 = 0.f, a2 = 0.f, a3 = 0.f;
        #pragma unroll
        for (int j4 = 0; j4 < 16; j4++) {
            const float4 v0 = bl0[j4];
            const float4 v1 = bl1[j4];
            const float4 v2 = bl2[j4];
            const float4 v3 = bl3[j4];
            a0 = fmaf(v0.x, w[4*j4+0], a0);
            a0 = fmaf(v0.y, w[4*j4+1], a0);
            a0 = fmaf(v0.z, w[4*j4+2], a0);
            a0 = fmaf(v0.w, w[4*j4+3], a0);
            a1 = fmaf(v1.x, w[4*j4+0], a1);
            a1 = fmaf(v1.y, w[4*j4+1], a1);
            a1 = fmaf(v1.z, w[4*j4+2], a1);
            a1 = fmaf(v1.w, w[4*j4+3], a1);
            a2 = fmaf(v2.x, w[4*j4+0], a2);
            a2 = fmaf(v2.y, w[4*j4+1], a2);
            a2 = fmaf(v2.z, w[4*j4+2], a2);
            a2 = fmaf(v2.w, w[4*j4+3], a2);
            a3 = fmaf(v3.x, w[4*j4+0], a3);
            a3 = fmaf(v3.y, w[4*j4+1], a3);
            a3 = fmaf(v3.z, w[4*j4+2], a3);
            a3 = fmaf(v3.w, w[4*j4+3], a3);
        }
        sp[0][ksec][d_local] = a0;
        sp[1][ksec][d_local] = a1;
        sp[2][ksec][d_local] = a2;
        sp[3][ksec][d_local] = a3;
        __syncthreads();   // sync#1: all partials visible to reducers

        if (is_red) {
            // ---- reduce + gates -> staging ----
            float s = 0.f;
            #pragma unroll
            for (int q = 0; q < 8; q++) s += sp[rb][q][d_local];
            const float cand = fast_tanh(s + bpv + evv);
            const float nb   = lkv * bel_prev + wrv * cand;
            bel_prev = nb;
            stage[cur][rb][d_local] = nb;

            // sync#2: named barrier over the 256 reducer threads only
            asm volatile("bar.sync 1, 256;" ::: "memory");

            if (t < TT - 1) {
                // arm my local slot barriers for phase nxt: slot q expects 1KB
                if (tid < CLUSTER_C) {
                    const uint32_t mb_a =
                        sb_base + (uint32_t)(nxt * CLUSTER_C + tid) * 8;
                    asm volatile(
                        "mbarrier.arrive.expect_tx.shared.b64 _, [%0], %1;"
                        :: "r"(mb_a), "r"((uint32_t)SLICE_BYTES) : "memory");
                }
                // warp w's lane 0 sends MY slice to peer w, tagged to
                // the peer's slot barrier [nxt][my rank]
                if ((tid & 31) == 0) {
                    const int peer = tid >> 5;   // 0..7
                    asm volatile("fence.proxy.async.shared::cta;" ::: "memory");
                    const uint32_t mb_l =
                        sb_base + (uint32_t)(nxt * CLUSTER_C + (int)rank) * 8;
                    const uint32_t src =
                        (uint32_t)__cvta_generic_to_shared(&stage[cur][0][0]);
                    const uint32_t dst_l =
                        (uint32_t)__cvta_generic_to_shared(&bel[nxt][rank][0][0]);
                    uint32_t dst_r, mb_r;
                    asm("mapa.shared::cluster.u32 %0, %1, %2;"
                        : "=r"(dst_r) : "r"(dst_l), "r"(peer));
                    asm("mapa.shared::cluster.u32 %0, %1, %2;"
                        : "=r"(mb_r) : "r"(mb_l), "r"(peer));
                    asm volatile(
                        "cp.async.bulk.shared::cluster.shared::cta.mbarrier::complete_tx::bytes "
                        "[%0], [%1], %2, [%3];"
                        :: "r"(dst_r), "r"(src), "r"((uint32_t)SLICE_BYTES), "r"(mb_r)
                        : "memory");
                }
            }
            // off-chain global store
            out[io_base + (size_t)t * DD] = nb;
        }
        // warps 8..15 fall through to their next slot wait; their sp
        // overwrite at t+1 is ordered by wait(t+1) <= senders' copies(t)
        // <= bar.sync1(t) <= reducers' sp reads(t).
    }
}

// ---------------------------------------------------------------------------
// Launch
// ---------------------------------------------------------------------------
extern "C" void kernel_launch(void* const* d_in, const int* in_sizes, int n_in,
                              void* d_out, int out_size)
{
    const float* evseq = (const float*)d_in[0];
    const float* We    = (const float*)d_in[1];
    const float* be    = (const float*)d_in[2];
    const float* Wp    = (const float*)d_in[3];
    const float* bp    = (const float*)d_in[4];
    const float* Wl    = (const float*)d_in[5];
    const float* bl    = (const float*)d_in[6];
    const float* Ww    = (const float*)d_in[7];
    const float* bw    = (const float*)d_in[8];
    float* out = (float*)d_out;

    float *p_ev, *p_leak, *p_write;
    cudaGetSymbolAddress((void**)&p_ev,    g_ev);
    cudaGetSymbolAddress((void**)&p_leak,  g_leak);
    cudaGetSymbolAddress((void**)&p_write, g_write);

    dim3 grid(MM / 128, DD / 128);
    dim3 blk(256);
    proj_gemm<0><<<grid, blk>>>(evseq, We, be, p_ev);
    proj_gemm<1><<<grid, blk>>>(evseq, Wl, bl, p_leak);
    proj_gemm<1><<<grid, blk>>>(evseq, Ww, bw, p_write);

    scan_cluster_kernel<<<NCLUST * CLUSTER_C, SCAN_THREADS>>>(Wp, bp, out);
}